// round 8
// baseline (speedup 1.0000x reference)
#include <cuda_runtime.h>
#include <math.h>

// Problem dims
#define S_LEN   512
#define BATCH   256
#define DIN     256
#define HID     512
#define HIST    2048
#define NB      128            // persistent CTAs (<= SM count, all co-resident)

// ---------------- device scratch (no allocs allowed) ----------------
__device__ float d_Wp[768 * 1536];            // packed weights, k-major (4.5 MB)
__device__ float d_h[2][BATCH * HID];         // ping-pong hidden state
__device__ float d_g[BATCH * HIST];           // alpha logits
__device__ float d_alpha[BATCH * HIST];
__device__ float d_sig[BATCH * DIN];
__device__ float d_mu[BATCH * DIN];
__device__ float d_inv_sigma[BATCH * DIN];
__device__ float d_logdet[BATCH];

// grid barrier state
__device__ unsigned int g_arrive;
__device__ volatile unsigned int g_release;

__global__ void reset_barrier_kernel() {
    g_arrive = 0;
    g_release = 0;
}

// ---------------- weight packing ----------------
// Wp[k][j], k in [0,768), j in [0,1536):
//   Wp[k][j] = (k<256) ? w_ih[j][k] : w_hh[j][k-256]
// j in [0,512): r-gate rows; [512,1024): z-gate rows; [1024,1536): n-gate rows
// (for n: k<256 contributes i_n, k>=256 contributes h_n — accumulated separately).
__global__ void pack_w_kernel(const float* __restrict__ w_ih,
                              const float* __restrict__ w_hh) {
    int idx = blockIdx.x * 256 + threadIdx.x;      // 768*1536 total
    int k = idx / 1536;
    int j = idx - k * 1536;
    float v = (k < 256) ? w_ih[j * 256 + k] : w_hh[j * 512 + (k - 256)];
    d_Wp[idx] = v;
}

__global__ void init_h_kernel(const float* __restrict__ hidden) {
    int i = blockIdx.x * 256 + threadIdx.x;        // 131072
    d_h[0][i] = hidden[i];
}

// ---------------- persistent fused GRU ----------------

__device__ __forceinline__ void grid_barrier(unsigned int gen) {
    __syncthreads();
    if (threadIdx.x == 0) {
        __threadfence();
        unsigned int prev = atomicAdd(&g_arrive, 1u);
        if (prev == NB - 1) {
            g_arrive = 0;              // all arrived; safe to reset
            __threadfence();
            g_release = gen;
        } else {
            while (g_release < gen) { }
            __threadfence();
        }
    }
    __syncthreads();
}

__device__ __forceinline__ void load_a(float (&ra)[8], const float* __restrict__ base,
                                       int ld, int row0, int koff, int tid) {
#pragma unroll
    for (int i = 0; i < 8; i++) {
        int idx = tid + (i << 7);
        int k = idx & 31, r = idx >> 5;
        ra[i] = base[(row0 + r) * ld + koff + k];
    }
}

__device__ __forceinline__ void load_b(float (&rb)[24], int kk0, int col0, int tid) {
#pragma unroll
    for (int p = 0; p < 3; p++)
#pragma unroll
        for (int i = 0; i < 8; i++) {
            int idx = tid + (i << 7);
            int c = idx & 31, k = idx >> 5;
            rb[p * 8 + i] = d_Wp[(size_t)(kk0 + k) * 1536 + (p << 9) + col0 + c];
        }
}

__device__ __forceinline__ void store_smem(float (&sA)[32][36], float (&sB)[3][32][34],
                                           const float (&ra)[8], const float (&rb)[24],
                                           int tid) {
#pragma unroll
    for (int i = 0; i < 8; i++) {
        int idx = tid + (i << 7);
        int k = idx & 31, r = idx >> 5;
        sA[k][r] = ra[i];
    }
#pragma unroll
    for (int p = 0; p < 3; p++)
#pragma unroll
        for (int i = 0; i < 8; i++) {
            int idx = tid + (i << 7);
            int c = idx & 31, k = idx >> 5;
            sB[p][k][c] = rb[p * 8 + i];
        }
}

__device__ __forceinline__ void compute_chunk(const float (&sA)[32][36],
                                              const float (&sB)[3][32][34],
                                              int tr4, int tc2,
                                              float (&aR)[4][2], float (&aZ)[4][2],
                                              float (&aN)[4][2]) {
#pragma unroll 8
    for (int k = 0; k < 32; k++) {
        float4 a = *(const float4*)&sA[k][tr4];
        float2 br = *(const float2*)&sB[0][k][tc2];
        float2 bz = *(const float2*)&sB[1][k][tc2];
        float2 bn = *(const float2*)&sB[2][k][tc2];
        float av[4] = {a.x, a.y, a.z, a.w};
#pragma unroll
        for (int i = 0; i < 4; i++) {
            aR[i][0] += av[i] * br.x;  aR[i][1] += av[i] * br.y;
            aZ[i][0] += av[i] * bz.x;  aZ[i][1] += av[i] * bz.y;
            aN[i][0] += av[i] * bn.x;  aN[i][1] += av[i] * bn.y;
        }
    }
}

__global__ __launch_bounds__(128) void gru_persistent(const float* __restrict__ x) {
    const int bid = blockIdx.x;
    const int rt = bid >> 4, ct = bid & 15;       // 8 row tiles x 16 col tiles
    const int row0 = rt * 32, col0 = ct * 32;
    const int tid = threadIdx.x;
    const int tr4 = (tid >> 4) << 2;              // row offset within tile (0,4,...,28)
    const int tc2 = (tid & 15) << 1;              // col offset within tile (0,2,...,30)

    __shared__ __align__(16) float sA[2][32][36];
    __shared__ __align__(16) float sB[2][3][32][34];

    float ra[8], rb[24];

    for (int t = 0; t < S_LEN; ++t) {
        const int par = t & 1;
        const float* __restrict__ h_in = d_h[par];
        const float* __restrict__ x_t = x + (size_t)t * (BATCH * DIN);

        float aR[4][2], aZ[4][2], aI[4][2], aH[4][2];
#pragma unroll
        for (int i = 0; i < 4; i++)
#pragma unroll
            for (int j = 0; j < 2; j++) {
                aR[i][j] = 0.f; aZ[i][j] = 0.f; aI[i][j] = 0.f; aH[i][j] = 0.f;
            }

        // prefetch chunk 0
        load_a(ra, x_t, DIN, row0, 0, tid);
        load_b(rb, 0, col0, tid);

        // 24 chunks of K=32: chunks 0..7 use x (n-panel -> aI),
        //                    chunks 8..23 use h (n-panel -> aH)
        for (int cc = 0; cc < 24; cc++) {
            const int b = cc & 1;
            store_smem(sA[b], sB[b], ra, rb, tid);
            __syncthreads();
            if (cc < 23) {
                int nk = (cc + 1) * 32;
                if (nk < 256) load_a(ra, x_t, DIN, row0, nk, tid);
                else          load_a(ra, h_in, HID, row0, nk - 256, tid);
                load_b(rb, nk, col0, tid);
            }
            if (cc < 8) compute_chunk(sA[b], sB[b], tr4, tc2, aR, aZ, aI);
            else        compute_chunk(sA[b], sB[b], tr4, tc2, aR, aZ, aH);
        }

        // fused gate epilogue: h_new = (1-z)*n + z*h
        float* __restrict__ hout = d_h[par ^ 1];
#pragma unroll
        for (int i = 0; i < 4; i++) {
            int row = row0 + tr4 + i;
#pragma unroll
            for (int j = 0; j < 2; j++) {
                int col = col0 + tc2 + j;
                float r = 1.f / (1.f + expf(-aR[i][j]));
                float z = 1.f / (1.f + expf(-aZ[i][j]));
                float n = tanhf(aI[i][j] + r * aH[i][j]);
                float hp = h_in[row * HID + col];
                hout[row * HID + col] = (1.f - z) * n + z * hp;
            }
        }

        grid_barrier((unsigned)(t + 1));
    }
}

// ---------------- generic tiled GEMM: C[256][N] = A[256][K] * op(B) ----------------
template <int TRANSB>
__global__ __launch_bounds__(128) void gemm_tile_kernel(
        const float* __restrict__ A, int lda,
        const float* __restrict__ Bm, int ldb,
        float* __restrict__ C, int ldc, int K, int colTiles) {
    int bid = blockIdx.x;
    int rt = bid / colTiles, ct = bid % colTiles;
    int row0 = rt * 32, col0 = ct * 64;

    __shared__ __align__(16) float sA[16][36];
    __shared__ __align__(16) float sB[16][68];

    int tid = threadIdx.x;
    int tr = tid >> 4, tc = tid & 15;

    float acc[4][4];
#pragma unroll
    for (int i = 0; i < 4; i++)
#pragma unroll
        for (int j = 0; j < 4; j++) acc[i][j] = 0.f;

    for (int kk0 = 0; kk0 < K; kk0 += 16) {
#pragma unroll
        for (int it = 0; it < 4; it++) {
            int idx = tid + it * 128;
            int k = idx & 15, r = idx >> 4;
            sA[k][r] = A[(size_t)(row0 + r) * lda + kk0 + k];
        }
        if (TRANSB) {
#pragma unroll
            for (int it = 0; it < 8; it++) {
                int idx = tid + it * 128;
                int k = idx & 15, j = idx >> 4;
                sB[k][j] = Bm[(size_t)(col0 + j) * ldb + kk0 + k];
            }
        } else {
#pragma unroll
            for (int it = 0; it < 8; it++) {
                int idx = tid + it * 128;
                int j = idx & 63, k = idx >> 6;
                sB[k][j] = Bm[(size_t)(kk0 + k) * ldb + col0 + j];
            }
        }
        __syncthreads();
#pragma unroll
        for (int k = 0; k < 16; k++) {
            float4 av = *(const float4*)&sA[k][tr << 2];
            float4 bv = *(const float4*)&sB[k][tc << 2];
            float a[4] = {av.x, av.y, av.z, av.w};
            float b[4] = {bv.x, bv.y, bv.z, bv.w};
#pragma unroll
            for (int i = 0; i < 4; i++)
#pragma unroll
                for (int j = 0; j < 4; j++) acc[i][j] += a[i] * b[j];
        }
        __syncthreads();
    }

#pragma unroll
    for (int i = 0; i < 4; i++) {
        float4 v = make_float4(acc[i][0], acc[i][1], acc[i][2], acc[i][3]);
        *(float4*)&C[(size_t)(row0 + (tr << 2) + i) * ldc + col0 + (tc << 2)] = v;
    }
}

// ---------------- softmax over 2048 history (per batch row) ----------------
__global__ __launch_bounds__(256) void softmax_kernel() {
    int b = blockIdx.x;
    const float* L = d_g + (size_t)b * HIST;
    float* A = d_alpha + (size_t)b * HIST;
    __shared__ float red[256];
    int tid = threadIdx.x;

    float m = -1e30f;
    for (int j = tid; j < HIST; j += 256) m = fmaxf(m, L[j]);
    red[tid] = m; __syncthreads();
    for (int s = 128; s > 0; s >>= 1) {
        if (tid < s) red[tid] = fmaxf(red[tid], red[tid + s]);
        __syncthreads();
    }
    m = red[0]; __syncthreads();

    float sum = 0.f;
    for (int j = tid; j < HIST; j += 256) {
        float e = expf(L[j] - m);
        A[j] = e;
        sum += e;
    }
    red[tid] = sum; __syncthreads();
    for (int s = 128; s > 0; s >>= 1) {
        if (tid < s) red[tid] += red[tid + s];
        __syncthreads();
    }
    float inv = 1.f / red[0];
    for (int j = tid; j < HIST; j += 256) A[j] *= inv;
}

// ---------------- sigma: inv_sigma = exp(-logit), logdet = sum(logit) ----------------
__global__ __launch_bounds__(256) void sigma_kernel() {
    int b = blockIdx.x, d = threadIdx.x;
    float t = d_sig[(size_t)b * DIN + d];
    d_inv_sigma[(size_t)b * DIN + d] = expf(-t);
    __shared__ float red[256];
    red[d] = t; __syncthreads();
    for (int s = 128; s > 0; s >>= 1) {
        if (d < s) red[d] += red[d + s];
        __syncthreads();
    }
    if (d == 0) d_logdet[b] = red[0];
}

// ---------------- final log-prob: warp per (s,b) ----------------
__global__ __launch_bounds__(256) void logprob_kernel(
        const float* __restrict__ x, float* __restrict__ out) {
    int w = (blockIdx.x << 3) + (threadIdx.x >> 5);   // s*256 + b
    int lane = threadIdx.x & 31;
    int b = w & 255;
    const float4* xr = (const float4*)(x + ((size_t)w << 8));
    const float4* mu = (const float4*)(d_mu + ((size_t)b << 8));
    const float4* iv = (const float4*)(d_inv_sigma + ((size_t)b << 8));
    float acc = 0.f;
#pragma unroll
    for (int c = 0; c < 2; c++) {
        int idx = lane + (c << 5);
        float4 xv = xr[idx], mv = mu[idx], sv = iv[idx];
        float d0 = (xv.x - mv.x) * sv.x;
        float d1 = (xv.y - mv.y) * sv.y;
        float d2 = (xv.z - mv.z) * sv.z;
        float d3 = (xv.w - mv.w) * sv.w;
        acc += d0 * d0 + d1 * d1 + d2 * d2 + d3 * d3;
    }
#pragma unroll
    for (int o = 16; o; o >>= 1) acc += __shfl_xor_sync(0xffffffffu, acc, o);
    if (lane == 0) {
        const float log2pi = 1.8378770664093453f;
        out[w] = -0.5f * (acc + 256.0f * log2pi) - d_logdet[b];
    }
}

// ---------------- launch ----------------
extern "C" void kernel_launch(void* const* d_in, const int* in_sizes, int n_in,
                              void* d_out, int out_size) {
    const float* x        = (const float*)d_in[0];
    const float* hidden   = (const float*)d_in[1];
    const float* external = (const float*)d_in[2];
    const float* w_ih     = (const float*)d_in[3];
    const float* w_hh     = (const float*)d_in[4];
    const float* w_alpha  = (const float*)d_in[5];
    const float* w_sigma  = (const float*)d_in[6];
    float* out = (float*)d_out;

    float *pH0, *pG, *pSig, *pAlpha, *pMu;
    cudaGetSymbolAddress((void**)&pH0, d_h);        // d_h[0]
    cudaGetSymbolAddress((void**)&pG, d_g);
    cudaGetSymbolAddress((void**)&pSig, d_sig);
    cudaGetSymbolAddress((void**)&pAlpha, d_alpha);
    cudaGetSymbolAddress((void**)&pMu, d_mu);

    reset_barrier_kernel<<<1, 1>>>();
    pack_w_kernel<<<(768 * 1536) / 256, 256>>>(w_ih, w_hh);
    init_h_kernel<<<(BATCH * HID) / 256, 256>>>(hidden);

    // entire 512-step GRU in ONE kernel (final h lands in d_h[0])
    gru_persistent<<<NB, 128>>>(x);

    // alpha logits [256 x 2048] = h @ w_alpha^T   (K=512)
    gemm_tile_kernel<1><<<8 * 32, 128>>>(pH0, HID, w_alpha, HID, pG, HIST, HID, 32);
    softmax_kernel<<<BATCH, 256>>>();
    // sigma logits [256 x 256] = h @ w_sigma^T    (K=512)
    gemm_tile_kernel<1><<<8 * 4, 128>>>(pH0, HID, w_sigma, HID, pSig, DIN, HID, 4);
    sigma_kernel<<<BATCH, 256>>>();
    // mu [256 x 256] = alpha @ external           (K=2048)
    gemm_tile_kernel<0><<<8 * 4, 128>>>(pAlpha, HIST, external, DIN, pMu, DIN, HIST, 4);

    logprob_kernel<<<(S_LEN * BATCH) / 8, 256>>>(x, out);
}